// round 2
// baseline (speedup 1.0000x reference)
#include <cuda_runtime.h>
#include <math.h>

#define NB 64
#define NG 32
#define TOTAL_ANCH 64512   // 49152 + 12288 + 3072

__device__ double g_acc;
__device__ int    g_numpos[NB * 3];
__device__ float  g_keys[(size_t)NB * TOTAL_ANCH];

__device__ __forceinline__ float sl1(float x) {
    float ax = fabsf(x);
    return (ax < 1.0f) ? 0.5f * x * x : ax - 0.5f;
}

// bce with target 0: softplus(x)
__device__ __forceinline__ float softplus0(float x) {
    return fmaxf(x, 0.0f) + log1pf(expf(-fabsf(x)));
}

// float -> order-preserving uint (descending float == descending uint)
__device__ __forceinline__ unsigned f2u(float f) {
    unsigned u = __float_as_uint(f);
    return (u & 0x80000000u) ? ~u : (u | 0x80000000u);
}
__device__ __forceinline__ float u2f(unsigned u) {
    return __uint_as_float((u & 0x80000000u) ? (u & 0x7FFFFFFFu) : ~u);
}

__global__ void k_init() {
    int t = threadIdx.x;
    if (t == 0) g_acc = 0.0;
    if (t < NB * 3) g_numpos[t] = 0;
}

// Pass 1: anchor matching + loc/cls/pos-obj losses + neg-key scatter.
// One thread per pixel, 3 anchors per thread. Anchors recomputed analytically
// (exactly matches reference fp32 values: all quantities exactly representable).
__global__ __launch_bounds__(256) void k_assign(
    const float* __restrict__ pred,      // (B, 24, H, W)
    const float* __restrict__ gt_boxes,  // (B, 32, 4)
    const int*   __restrict__ gt_labels, // (B, 32)
    int W, int HW, float stride, int keyoff, int scale)
{
    const int b   = blockIdx.y;
    const int tid = threadIdx.x;
    const int p   = blockIdx.x * blockDim.x + tid;

    __shared__ float4 s_box[NG];
    __shared__ float  s_area[NG];
    __shared__ int    s_lbl[NG];

    if (tid < NG) {
        float4 bb = ((const float4*)gt_boxes)[b * NG + tid];
        s_box[tid]  = bb;
        s_area[tid] = (bb.z - bb.x) * (bb.w - bb.y);
        s_lbl[tid]  = gt_labels[b * NG + tid];
    }
    __syncthreads();

    float loss = 0.0f;
    int   cpos = 0;

    if (p < HW) {
        const int w = p % W;
        const int h = p / W;
        const float cx = (w + 0.5f) * stride;
        const float cy = (h + 0.5f) * stride;
        float* keyp = g_keys + (size_t)b * TOTAL_ANCH + keyoff + (size_t)p * 3;

        #pragma unroll
        for (int a = 0; a < 3; ++a) {
            const float s   = (float)(3 + a) * stride;
            const float hlf = 0.5f * s;
            const float ax1 = cx - hlf, ay1 = cy - hlf;
            const float ax2 = cx + hlf, ay2 = cy + hlf;
            const float areaA = s * s;

            // argmax over 32 GTs via division-free cross-multiplication:
            // iou_j > iou_b  <=>  inter_j * S_b > inter_b * S_j
            float bi, bS; int bidx = 0;
            {
                float4 g = s_box[0];
                float lx = fmaxf(ax1, g.x), ly = fmaxf(ay1, g.y);
                float rx = fminf(ax2, g.z), ry = fminf(ay2, g.w);
                float iw = fmaxf(rx - lx, 0.0f), ih = fmaxf(ry - ly, 0.0f);
                bi = iw * ih;
                bS = areaA + s_area[0];
            }
            #pragma unroll 8
            for (int j = 1; j < NG; ++j) {
                float4 g = s_box[j];
                float lx = fmaxf(ax1, g.x), ly = fmaxf(ay1, g.y);
                float rx = fminf(ax2, g.z), ry = fminf(ay2, g.w);
                float iw = fmaxf(rx - lx, 0.0f), ih = fmaxf(ry - ly, 0.0f);
                float inter = iw * ih;
                float S     = areaA + s_area[j];
                if (inter * bS > bi * S) { bi = inter; bS = S; bidx = j; }
            }

            // one true division, same association as reference:
            // ((areaA + areaB) - inter) + 1e-9
            const float denom    = (bS - bi) + 1e-9f;
            const float best_iou = bi / denom;
            const bool  pos = (best_iou >= 0.5f);
            const bool  neg = (best_iou <  0.4f);

            const size_t base = ((size_t)b * 24 + a * 8) * (size_t)HW + p;
            const float  xo   = pred[base + 4 * (size_t)HW];   // objectness logit
            keyp[a] = neg ? xo : -1e30f;

            if (pos) {
                cpos++;
                // objectness bce(x, 1)
                loss += fmaxf(xo, 0.0f) - xo + log1pf(expf(-fabsf(xo)));

                float4 g = s_box[bidx];
                float gx = (g.x + g.z) * 0.5f;
                float gy = (g.y + g.w) * 0.5f;
                float gw = fmaxf(g.z - g.x, 1e-6f);
                float gh = fmaxf(g.w - g.y, 1e-6f);
                float aw = fmaxf(ax2 - ax1, 1e-6f);   // == s (exact)
                float ah = fmaxf(ay2 - ay1, 1e-6f);

                float ttx = (gx - cx) / aw;           // ax == cx exactly
                float tty = (gy - cy) / ah;
                float ttw = logf(gw / aw);
                float tth = logf(gh / ah);

                float p0 = pred[base];
                float p1 = pred[base + 1 * (size_t)HW];
                float p2 = pred[base + 2 * (size_t)HW];
                float p3 = pred[base + 3 * (size_t)HW];
                loss += sl1(p0 - ttx) + sl1(p1 - tty) + sl1(p2 - ttw) + sl1(p3 - tth);

                // class CE (log-softmax over 3 classes)
                float c0 = pred[base + 5 * (size_t)HW];
                float c1 = pred[base + 6 * (size_t)HW];
                float c2 = pred[base + 7 * (size_t)HW];
                float m  = fmaxf(c0, fmaxf(c1, c2));
                float lse = m + logf(expf(c0 - m) + expf(c1 - m) + expf(c2 - m));
                int   t   = max(s_lbl[bidx], 0);
                float pt  = (t == 0) ? c0 : ((t == 1) ? c1 : c2);
                loss += lse - pt;
            }
        }
    }

    // block reduction (8 warps)
    #pragma unroll
    for (int o = 16; o; o >>= 1) {
        loss += __shfl_down_sync(0xFFFFFFFFu, loss, o);
        cpos += __shfl_down_sync(0xFFFFFFFFu, cpos, o);
    }
    __shared__ float rs[8];
    __shared__ int   rc[8];
    const int wid = tid >> 5, lid = tid & 31;
    if (lid == 0) { rs[wid] = loss; rc[wid] = cpos; }
    __syncthreads();
    if (tid == 0) {
        float L = 0.0f; int C = 0;
        #pragma unroll
        for (int i = 0; i < 8; ++i) { L += rs[i]; C += rc[i]; }
        if (L != 0.0f) atomicAdd(&g_acc, (double)L);
        if (C)         atomicAdd(&g_numpos[b * 3 + scale], C);
    }
}

// Pass 2: per (image, scale) exact top-k sum of neg objectness losses.
// Ranking by bce(x,0)=softplus(x) == ranking by logit x (monotone), so
// radix-select the k-th largest logit, then sum softplus over winners.
__global__ __launch_bounds__(256) void k_select() {
    __shared__ unsigned hist[256];
    __shared__ unsigned s_digit;
    __shared__ int      s_kk;
    __shared__ float    rs[8];

    const int task = blockIdx.x;            // 0..191
    const int b  = task / 3;
    const int sc = task % 3;
    const int Ns[3]   = {49152, 12288, 3072};
    const int offs[3] = {0, 49152, 61440};
    const int N = Ns[sc];
    const float* keys = g_keys + (size_t)b * TOTAL_ANCH + offs[sc];

    const int np = g_numpos[task];
    int k = 3 * max(1, np);
    if (k > N) k = N;

    unsigned prefix = 0;
    int kk = k;
    for (int r = 0; r < 4; ++r) {
        const int shift = 24 - 8 * r;
        const unsigned mask = r ? (0xFFFFFFFFu << (shift + 8)) : 0u;
        for (int i = threadIdx.x; i < 256; i += blockDim.x) hist[i] = 0;
        __syncthreads();
        for (int i = threadIdx.x; i < N; i += blockDim.x) {
            unsigned u = f2u(keys[i]);
            if ((u & mask) == prefix) atomicAdd(&hist[(u >> shift) & 255u], 1u);
        }
        __syncthreads();
        if (threadIdx.x == 0) {
            int cum = 0, d = 0, nk = kk;
            for (int bin = 255; bin >= 0; --bin) {
                int c = (int)hist[bin];
                if (cum + c >= kk) { d = bin; nk = kk - cum; break; }
                cum += c;
            }
            s_digit = (unsigned)d;
            s_kk = nk;
        }
        __syncthreads();
        prefix |= s_digit << shift;
        kk = s_kk;
        __syncthreads();
    }

    // sum softplus over strictly-greater keys; kk ties at the threshold value
    float local = 0.0f;
    for (int i = threadIdx.x; i < N; i += blockDim.x) {
        float x = keys[i];
        if (f2u(x) > prefix) local += softplus0(x);
    }
    #pragma unroll
    for (int o = 16; o; o >>= 1) local += __shfl_down_sync(0xFFFFFFFFu, local, o);
    const int wid = threadIdx.x >> 5, lid = threadIdx.x & 31;
    if (lid == 0) rs[wid] = local;
    __syncthreads();
    if (threadIdx.x == 0) {
        float tot = 0.0f;
        #pragma unroll
        for (int i = 0; i < 8; ++i) tot += rs[i];
        tot += (float)kk * softplus0(u2f(prefix));
        atomicAdd(&g_acc, (double)tot);
    }
}

__global__ void k_fin(float* out) {
    out[0] = (float)(g_acc * (1.0 / 64.0));
}

extern "C" void kernel_launch(void* const* d_in, const int* in_sizes, int n_in,
                              void* d_out, int out_size)
{
    const float* pred0 = (const float*)d_in[0];
    const float* pred1 = (const float*)d_in[2];
    const float* pred2 = (const float*)d_in[4];
    const float* gtb   = (const float*)d_in[6];
    const int*   gtl   = (const int*)d_in[7];

    k_init<<<1, 256>>>();

    dim3 g0(16384 / 256, NB);
    k_assign<<<g0, 256>>>(pred0, gtb, gtl, 128, 16384, 8.0f, 0, 0);
    dim3 g1(4096 / 256, NB);
    k_assign<<<g1, 256>>>(pred1, gtb, gtl, 64, 4096, 16.0f, 49152, 1);
    dim3 g2(1024 / 256, NB);
    k_assign<<<g2, 256>>>(pred2, gtb, gtl, 32, 1024, 32.0f, 61440, 2);

    k_select<<<192, 256>>>();
    k_fin<<<1, 1>>>((float*)d_out);
}

// round 3
// speedup vs baseline: 1.7581x; 1.7581x over previous
#include <cuda_runtime.h>
#include <math.h>

#define NB 64
#define NG 32
#define TOT 64512          // 49152 + 12288 + 3072
#define NTASK 192          // 64 images x 3 scales
#define HB 4096            // 12-bit histogram
#define MAXN 49152

__device__ double   g_acc;
__device__ int      g_numpos[NTASK];
__device__ float    g_keys[(size_t)NB * TOT];
__device__ unsigned g_hist[NTASK * HB];          // 3 MB
__device__ unsigned g_bufcnt[NTASK];
__device__ unsigned g_buf[(size_t)NTASK * MAXN]; // 37.7 MB
__device__ int      g_planT[NTASK];
__device__ int      g_planKK[NTASK];

__device__ __forceinline__ float sl1(float x) {
    float ax = fabsf(x);
    return (ax < 1.0f) ? 0.5f * x * x : ax - 0.5f;
}
__device__ __forceinline__ float softplus0(float x) {
    return fmaxf(x, 0.0f) + log1pf(expf(-fabsf(x)));
}
// raw float bits -> order-preserving key (descending float == descending uint)
__device__ __forceinline__ unsigned bits2key(unsigned u) {
    return (u & 0x80000000u) ? ~u : (u | 0x80000000u);
}
__device__ __forceinline__ float key2f(unsigned k) {
    unsigned u = (k & 0x80000000u) ? (k & 0x7FFFFFFFu) : ~k;
    return __uint_as_float(u);
}
__device__ __forceinline__ void task_dims(int s, int& N, int& off) {
    N   = (s == 0) ? 49152 : ((s == 1) ? 12288 : 3072);
    off = (s == 0) ? 0     : ((s == 1) ? 49152 : 61440);
}

// block-wide exclusive scan over 256 ints
__device__ __forceinline__ int scan_excl256(int v, int* sh) {
    const int t = threadIdx.x;
    sh[t] = v; __syncthreads();
    #pragma unroll
    for (int o = 1; o < 256; o <<= 1) {
        int x = (t >= o) ? sh[t - o] : 0;
        __syncthreads();
        sh[t] += x;
        __syncthreads();
    }
    return sh[t] - v;
}

__device__ __forceinline__ float block_reduce(float v, float* rs) {
    #pragma unroll
    for (int o = 16; o; o >>= 1) v += __shfl_down_sync(0xFFFFFFFFu, v, o);
    const int wid = threadIdx.x >> 5, lid = threadIdx.x & 31;
    if (lid == 0) rs[wid] = v;
    __syncthreads();
    float tot = 0.0f;
    if (threadIdx.x == 0) {
        #pragma unroll
        for (int i = 0; i < 8; ++i) tot += rs[i];
    }
    return tot;
}

__global__ void k_init() {
    int idx = blockIdx.x * blockDim.x + threadIdx.x;
    if (idx < NTASK * HB) g_hist[idx] = 0;
    if (idx < NTASK) { g_numpos[idx] = 0; g_bufcnt[idx] = 0; }
    if (idx == 0) g_acc = 0.0;
}

// ---------------------------------------------------------------------------
// Pass 1: anchor matching (all scales in one launch) + loc/cls/pos-obj losses
// + neg-key scatter (coalesced [a][p] planes).
// ---------------------------------------------------------------------------
__global__ __launch_bounds__(256) void k_assign(
    const float* __restrict__ pred0,
    const float* __restrict__ pred1,
    const float* __restrict__ pred2,
    const float* __restrict__ gt_boxes,
    const int*   __restrict__ gt_labels)
{
    const int b   = blockIdx.y;
    const int cx_ = blockIdx.x;            // 0..83
    const int tid = threadIdx.x;

    int scale, blkbase, W, HW, keyoff;
    float stride;
    const float* pred;
    if (cx_ < 64)      { scale = 0; blkbase = 0;  W = 128; HW = 16384; stride = 8.0f;  keyoff = 0;     pred = pred0; }
    else if (cx_ < 80) { scale = 1; blkbase = 64; W = 64;  HW = 4096;  stride = 16.0f; keyoff = 49152; pred = pred1; }
    else               { scale = 2; blkbase = 80; W = 32;  HW = 1024;  stride = 32.0f; keyoff = 61440; pred = pred2; }

    const int p = (cx_ - blkbase) * 256 + tid;   // HW divisible by 256 for all scales

    __shared__ float4 s_box[NG];
    __shared__ float  s_area[NG];
    __shared__ int    s_lbl[NG];
    __shared__ float  rs[8];
    __shared__ int    rc[8];

    if (tid < NG) {
        float4 bb = ((const float4*)gt_boxes)[b * NG + tid];
        s_box[tid]  = bb;
        s_area[tid] = (bb.z - bb.x) * (bb.w - bb.y);
        s_lbl[tid]  = gt_labels[b * NG + tid];
    }
    __syncthreads();

    float loss = 0.0f;
    int   cpos = 0;

    const int w = p % W;
    const int h = p / W;
    const float cxp = (w + 0.5f) * stride;
    const float cyp = (h + 0.5f) * stride;
    float* keyb = g_keys + (size_t)b * TOT + keyoff;

    #pragma unroll 1
    for (int a = 0; a < 3; ++a) {
        const float s   = (float)(3 + a) * stride;
        const float hlf = 0.5f * s;
        const float ax1 = cxp - hlf, ay1 = cyp - hlf;
        const float ax2 = cxp + hlf, ay2 = cyp + hlf;
        const float areaA = s * s;

        // 4 independent comparison chains (8 GTs each) to cut dependency latency;
        // merged with earlier-index priority (strict >), same winner as sequential.
        float bi[4], bS[4];
        int   bx[4];
        #pragma unroll
        for (int c = 0; c < 4; ++c) {
            const int j0 = c * 8;
            {
                float4 g = s_box[j0];
                float lx = fmaxf(ax1, g.x), ly = fmaxf(ay1, g.y);
                float rx = fminf(ax2, g.z), ry = fminf(ay2, g.w);
                float iw = fmaxf(rx - lx, 0.0f), ih = fmaxf(ry - ly, 0.0f);
                bi[c] = iw * ih;
                bS[c] = areaA + s_area[j0];
                bx[c] = j0;
            }
            #pragma unroll
            for (int jj = 1; jj < 8; ++jj) {
                const int j = j0 + jj;
                float4 g = s_box[j];
                float lx = fmaxf(ax1, g.x), ly = fmaxf(ay1, g.y);
                float rx = fminf(ax2, g.z), ry = fminf(ay2, g.w);
                float iw = fmaxf(rx - lx, 0.0f), ih = fmaxf(ry - ly, 0.0f);
                float inter = iw * ih;
                float S     = areaA + s_area[j];
                if (inter * bS[c] > bi[c] * S) { bi[c] = inter; bS[c] = S; bx[c] = j; }
            }
        }
        float BI = bi[0], BS = bS[0]; int BX = bx[0];
        #pragma unroll
        for (int c = 1; c < 4; ++c)
            if (bi[c] * BS > BI * bS[c]) { BI = bi[c]; BS = bS[c]; BX = bx[c]; }

        // one true division; association matches reference exactly
        const float denom    = (BS - BI) + 1e-9f;
        const float best_iou = BI / denom;
        const bool  pos = (best_iou >= 0.5f);
        const bool  neg = (best_iou <  0.4f);

        const size_t base = ((size_t)b * 24 + a * 8) * (size_t)HW + p;
        const float  xo   = pred[base + 4 * (size_t)HW];   // objectness logit
        keyb[a * HW + p] = neg ? xo : -1e30f;

        if (pos) {
            cpos++;
            loss += fmaxf(xo, 0.0f) - xo + log1pf(expf(-fabsf(xo)));

            float4 g = s_box[BX];
            float gx = (g.x + g.z) * 0.5f;
            float gy = (g.y + g.w) * 0.5f;
            float gw = fmaxf(g.z - g.x, 1e-6f);
            float gh = fmaxf(g.w - g.y, 1e-6f);
            float aw = fmaxf(ax2 - ax1, 1e-6f);
            float ah = fmaxf(ay2 - ay1, 1e-6f);

            float ttx = (gx - cxp) / aw;
            float tty = (gy - cyp) / ah;
            float ttw = logf(gw / aw);
            float tth = logf(gh / ah);

            float p0 = pred[base];
            float p1 = pred[base + 1 * (size_t)HW];
            float p2 = pred[base + 2 * (size_t)HW];
            float p3 = pred[base + 3 * (size_t)HW];
            loss += sl1(p0 - ttx) + sl1(p1 - tty) + sl1(p2 - ttw) + sl1(p3 - tth);

            float c0 = pred[base + 5 * (size_t)HW];
            float c1 = pred[base + 6 * (size_t)HW];
            float c2 = pred[base + 7 * (size_t)HW];
            float m  = fmaxf(c0, fmaxf(c1, c2));
            float lse = m + logf(expf(c0 - m) + expf(c1 - m) + expf(c2 - m));
            int   t   = max(s_lbl[BX], 0);
            float pt  = (t == 0) ? c0 : ((t == 1) ? c1 : c2);
            loss += lse - pt;
        }
    }

    // block reduction
    #pragma unroll
    for (int o = 16; o; o >>= 1) {
        loss += __shfl_down_sync(0xFFFFFFFFu, loss, o);
        cpos += __shfl_down_sync(0xFFFFFFFFu, cpos, o);
    }
    const int wid = tid >> 5, lid = tid & 31;
    if (lid == 0) { rs[wid] = loss; rc[wid] = cpos; }
    __syncthreads();
    if (tid == 0) {
        float L = 0.0f; int C = 0;
        #pragma unroll
        for (int i = 0; i < 8; ++i) { L += rs[i]; C += rc[i]; }
        if (L != 0.0f) atomicAdd(&g_acc, (double)L);
        if (C)         atomicAdd(&g_numpos[b * 3 + scale], C);
    }
}

// ---------------------------------------------------------------------------
// S1: per-task 4096-bin histogram, chip-wide parallel. grid=(12, NTASK)
// ---------------------------------------------------------------------------
__global__ __launch_bounds__(256) void k_hist() {
    __shared__ unsigned sh[HB];
    const int task = blockIdx.y;
    const int s = task % 3, b = task / 3;
    int N, off; task_dims(s, N, off);
    const int n4 = N >> 2;
    const int base4 = blockIdx.x * 1024;
    if (base4 >= n4) return;

    for (int i = threadIdx.x; i < HB; i += 256) sh[i] = 0;
    __syncthreads();

    const uint4* keys4 = (const uint4*)(g_keys + (size_t)b * TOT + off);
    #pragma unroll
    for (int k = 0; k < 4; ++k) {
        int i4 = base4 + threadIdx.x + k * 256;
        if (i4 < n4) {
            uint4 v = keys4[i4];
            atomicAdd(&sh[bits2key(v.x) >> 20], 1u);
            atomicAdd(&sh[bits2key(v.y) >> 20], 1u);
            atomicAdd(&sh[bits2key(v.z) >> 20], 1u);
            atomicAdd(&sh[bits2key(v.w) >> 20], 1u);
        }
    }
    __syncthreads();
    unsigned* gh = g_hist + task * HB;
    for (int i = threadIdx.x; i < HB; i += 256) {
        unsigned c = sh[i];
        if (c) atomicAdd(&gh[i], c);
    }
}

// ---------------------------------------------------------------------------
// S2: per-task descending scan of the histogram -> 12-bit threshold bin + kk
// ---------------------------------------------------------------------------
__global__ __launch_bounds__(256) void k_plan() {
    __shared__ int sh[256];
    const int task = blockIdx.x;
    const int s = task % 3;
    int N, off; task_dims(s, N, off);

    int k = 3 * max(1, g_numpos[task]);
    if (k > N) k = N;

    const unsigned* gh = g_hist + task * HB;
    int cnt[16], tot = 0;
    #pragma unroll
    for (int i = 0; i < 16; ++i) {
        int bin = HB - 1 - (threadIdx.x * 16 + i);
        cnt[i] = (int)gh[bin];
        tot += cnt[i];
    }
    int excl = scan_excl256(tot, sh);
    if (excl < k && excl + tot >= k) {
        int cum = excl;
        #pragma unroll
        for (int i = 0; i < 16; ++i) {
            if (cum + cnt[i] >= k) {
                g_planT[task]  = HB - 1 - (threadIdx.x * 16 + i);
                g_planKK[task] = k - cum;
                break;
            }
            cum += cnt[i];
        }
    }
}

// ---------------------------------------------------------------------------
// S3: parallel pass: sum softplus above threshold bin; compact bin members.
// grid=(12, NTASK)
// ---------------------------------------------------------------------------
__global__ __launch_bounds__(256) void k_sumgather() {
    __shared__ float rs[8];
    const int task = blockIdx.y;
    const int s = task % 3, b = task / 3;
    int N, off; task_dims(s, N, off);
    const int n4 = N >> 2;
    const int base4 = blockIdx.x * 1024;
    if (base4 >= n4) return;

    const unsigned T = (unsigned)g_planT[task];
    const uint4* keys4 = (const uint4*)(g_keys + (size_t)b * TOT + off);
    unsigned* buf = g_buf + (size_t)task * MAXN;

    float local = 0.0f;
    #pragma unroll
    for (int k = 0; k < 4; ++k) {
        int i4 = base4 + threadIdx.x + k * 256;
        if (i4 < n4) {
            uint4 v = keys4[i4];
            unsigned uu[4] = {bits2key(v.x), bits2key(v.y), bits2key(v.z), bits2key(v.w)};
            #pragma unroll
            for (int q = 0; q < 4; ++q) {
                unsigned bin = uu[q] >> 20;
                if (bin > T)       local += softplus0(key2f(uu[q]));
                else if (bin == T) buf[atomicAdd(&g_bufcnt[task], 1u)] = uu[q];
            }
        }
    }
    float tot = block_reduce(local, rs);
    if (threadIdx.x == 0 && tot != 0.0f) atomicAdd(&g_acc, (double)tot);
}

// ---------------------------------------------------------------------------
// S4: per-task exact refinement over compacted bin members (12 + 8 low bits)
// ---------------------------------------------------------------------------
__global__ __launch_bounds__(256) void k_refine() {
    __shared__ unsigned h2[HB];
    __shared__ unsigned h3[256];
    __shared__ int      sh[256];
    __shared__ float    rs[8];
    __shared__ int      sT2, sKK2, sT3, sKK3;

    const int task = blockIdx.x;
    const int m  = (int)g_bufcnt[task];
    const int kk = g_planKK[task];
    const unsigned top12 = (unsigned)g_planT[task];
    const unsigned* buf = g_buf + (size_t)task * MAXN;

    for (int i = threadIdx.x; i < HB; i += 256) h2[i] = 0;
    h3[threadIdx.x] = 0;
    __syncthreads();

    // pass 1: histogram of middle 12 bits
    for (int i = threadIdx.x; i < m; i += 256)
        atomicAdd(&h2[(buf[i] >> 8) & 0xFFFu], 1u);
    __syncthreads();

    // descending scan -> T2, kk2
    {
        int cnt[16], tot = 0;
        #pragma unroll
        for (int i = 0; i < 16; ++i) {
            int bin = HB - 1 - (threadIdx.x * 16 + i);
            cnt[i] = (int)h2[bin];
            tot += cnt[i];
        }
        int excl = scan_excl256(tot, sh);
        if (excl < kk && excl + tot >= kk) {
            int cum = excl;
            #pragma unroll
            for (int i = 0; i < 16; ++i) {
                if (cum + cnt[i] >= kk) { sT2 = HB - 1 - (threadIdx.x * 16 + i); sKK2 = kk - cum; break; }
                cum += cnt[i];
            }
        }
    }
    __syncthreads();
    const unsigned T2 = (unsigned)sT2;
    const int kk2 = sKK2;

    // pass 2: sum softplus for mid > T2, histogram low byte for mid == T2
    float local = 0.0f;
    for (int i = threadIdx.x; i < m; i += 256) {
        unsigned u = buf[i];
        unsigned mid = (u >> 8) & 0xFFFu;
        if (mid > T2)       local += softplus0(key2f(u));
        else if (mid == T2) atomicAdd(&h3[u & 0xFFu], 1u);
    }
    __syncthreads();

    // descending scan of 256 low-byte bins -> T3, kk3
    {
        int bin = 255 - threadIdx.x;
        int c = (int)h3[bin];
        int excl = scan_excl256(c, sh);
        if (excl < kk2 && excl + c >= kk2) { sT3 = bin; sKK3 = kk2 - excl; }
    }
    __syncthreads();
    const unsigned T3 = (unsigned)sT3;
    const int kk3 = sKK3;
    const unsigned ustar = (top12 << 20) | (T2 << 8) | T3;

    // pass 3: mid == T2 && low > T3
    for (int i = threadIdx.x; i < m; i += 256) {
        unsigned u = buf[i];
        if (((u >> 8) & 0xFFFu) == T2 && (u & 0xFFu) > T3)
            local += softplus0(key2f(u));
    }
    __syncthreads();
    float tot = block_reduce(local, rs);
    if (threadIdx.x == 0) {
        tot += (float)kk3 * softplus0(key2f(ustar));
        atomicAdd(&g_acc, (double)tot);
    }
}

__global__ void k_fin(float* out) {
    out[0] = (float)(g_acc * (1.0 / 64.0));
}

extern "C" void kernel_launch(void* const* d_in, const int* in_sizes, int n_in,
                              void* d_out, int out_size)
{
    const float* pred0 = (const float*)d_in[0];
    const float* pred1 = (const float*)d_in[2];
    const float* pred2 = (const float*)d_in[4];
    const float* gtb   = (const float*)d_in[6];
    const int*   gtl   = (const int*)d_in[7];

    k_init<<<1536, 512>>>();

    dim3 ga(84, NB);
    k_assign<<<ga, 256>>>(pred0, pred1, pred2, gtb, gtl);

    dim3 gh(12, NTASK);
    k_hist<<<gh, 256>>>();
    k_plan<<<NTASK, 256>>>();
    k_sumgather<<<gh, 256>>>();
    k_refine<<<NTASK, 256>>>();
    k_fin<<<1, 1>>>((float*)d_out);
}

// round 5
// speedup vs baseline: 5.0154x; 2.8528x over previous
#include <cuda_runtime.h>
#include <math.h>

#define NB 64
#define NG 32
#define TOT 64512          // 49152 + 12288 + 3072
#define NTASK 192          // 64 images x 3 scales
#define HB 4096            // 12-bit histogram
#define MAXN 49152

__device__ double   g_acc;
__device__ int      g_numpos[NTASK];
__device__ float    g_keys[(size_t)NB * TOT];
__device__ unsigned g_hist[NTASK * HB];          // 3 MB
__device__ unsigned g_bufcnt[NTASK];
__device__ unsigned g_buf[(size_t)NTASK * MAXN];
__device__ int      g_planT[NTASK];
__device__ int      g_planKK[NTASK];

__device__ __forceinline__ float sl1(float x) {
    float ax = fabsf(x);
    return (ax < 1.0f) ? 0.5f * x * x : ax - 0.5f;
}
__device__ __forceinline__ float softplus0(float x) {
    return fmaxf(x, 0.0f) + log1pf(expf(-fabsf(x)));
}
// float -> order-preserving key (descending float == descending uint)
__device__ __forceinline__ unsigned f2u(float f) {
    unsigned u = __float_as_uint(f);
    return (u & 0x80000000u) ? ~u : (u | 0x80000000u);
}
__device__ __forceinline__ float key2f(unsigned k) {
    unsigned u = (k & 0x80000000u) ? (k & 0x7FFFFFFFu) : ~k;
    return __uint_as_float(u);
}
__device__ __forceinline__ void task_dims(int s, int& N, int& off) {
    N   = (s == 0) ? 49152 : ((s == 1) ? 12288 : 3072);
    off = (s == 0) ? 0     : ((s == 1) ? 49152 : 61440);
}

// exclusive prefix over the block's 256 threads (warp shuffles, 2 barriers)
__device__ __forceinline__ int scan256(int v) {
    __shared__ int wsum[8];
    const int lane = threadIdx.x & 31, wid = threadIdx.x >> 5;
    int inc = v;
    #pragma unroll
    for (int o = 1; o < 32; o <<= 1) {
        int t = __shfl_up_sync(0xFFFFFFFFu, inc, o);
        if (lane >= o) inc += t;
    }
    __syncthreads();               // protect wsum reuse across calls
    if (lane == 31) wsum[wid] = inc;
    __syncthreads();
    int woff = 0;
    #pragma unroll
    for (int i = 0; i < 8; ++i) if (i < wid) woff += wsum[i];
    return woff + inc - v;
}

__device__ __forceinline__ float block_reduce(float v, float* rs) {
    #pragma unroll
    for (int o = 16; o; o >>= 1) v += __shfl_down_sync(0xFFFFFFFFu, v, o);
    const int wid = threadIdx.x >> 5, lid = threadIdx.x & 31;
    if (lid == 0) rs[wid] = v;
    __syncthreads();
    float tot = 0.0f;
    if (threadIdx.x == 0) {
        #pragma unroll
        for (int i = 0; i < 8; ++i) tot += rs[i];
    }
    return tot;
}

__global__ void k_init() {
    int idx = blockIdx.x * blockDim.x + threadIdx.x;
    if (idx < NTASK * HB) g_hist[idx] = 0;
    if (idx < NTASK) { g_numpos[idx] = 0; g_bufcnt[idx] = 0; }
    if (idx == 0) g_acc = 0.0;
}

// ---------------------------------------------------------------------------
// Pass 1: tiled anchor matching with spatial GT culling + losses + key scatter
// + fused per-task histogram. Blocks are 16x16 pixel tiles.
// ---------------------------------------------------------------------------
__global__ __launch_bounds__(256) void k_assign(
    const float* __restrict__ pred0,
    const float* __restrict__ pred1,
    const float* __restrict__ pred2,
    const float* __restrict__ gt_boxes,
    const int*   __restrict__ gt_labels)
{
    const int b   = blockIdx.y;
    const int cx_ = blockIdx.x;            // 0..83
    const int tid = threadIdx.x;

    int scale, blkbase, W, HW, keyoff, TW;
    float stride;
    const float* pred;
    if (cx_ < 64)      { scale = 0; blkbase = 0;  W = 128; HW = 16384; stride = 8.0f;  keyoff = 0;     pred = pred0; TW = 8; }
    else if (cx_ < 80) { scale = 1; blkbase = 64; W = 64;  HW = 4096;  stride = 16.0f; keyoff = 49152; pred = pred1; TW = 4; }
    else               { scale = 2; blkbase = 80; W = 32;  HW = 1024;  stride = 32.0f; keyoff = 61440; pred = pred2; TW = 2; }

    const int tile = cx_ - blkbase;
    const int tbx = tile % TW, tby = tile / TW;
    const int tx = tid & 15, ty = tid >> 4;
    const int w = tbx * 16 + tx;
    const int h = tby * 16 + ty;
    const int p = h * W + w;

    __shared__ float4   s_cbox[NG];
    __shared__ float    s_carea[NG];
    __shared__ int      s_clbl[NG];
    __shared__ int      s_cnt;
    __shared__ unsigned sh_hist[HB];
    __shared__ float    rs[8];
    __shared__ int      rc[8];

    for (int i = tid; i < HB; i += 256) sh_hist[i] = 0;

    // warp 0: cull GTs against this tile's anchor-reach bbox, compact to shared.
    // Culled GTs have inter==0 with every anchor in the tile, so they can never
    // change best_iou or (when pos) best_idx -> exact.
    if (tid < 32) {
        float4 g = ((const float4*)gt_boxes)[b * NG + tid];
        float rx0 = ((float)(tbx * 16) - 2.0f) * stride;
        float rx1 = ((float)(tbx * 16) + 18.0f) * stride;
        float ry0 = ((float)(tby * 16) - 2.0f) * stride;
        float ry1 = ((float)(tby * 16) + 18.0f) * stride;
        bool c = (g.x <= rx1) && (g.z >= rx0) && (g.y <= ry1) && (g.w >= ry0);
        unsigned m = __ballot_sync(0xFFFFFFFFu, c);
        if (c) {
            int pos = __popc(m & ((1u << tid) - 1u));
            s_cbox[pos]  = g;
            s_carea[pos] = (g.z - g.x) * (g.w - g.y);
            s_clbl[pos]  = gt_labels[b * NG + tid];
        }
        if (tid == 0) s_cnt = __popc(m);
    }
    __syncthreads();
    const int cnt = s_cnt;

    float loss = 0.0f;
    int   cpos = 0;
    const float cxp = (w + 0.5f) * stride;
    const float cyp = (h + 0.5f) * stride;
    float* keyb = g_keys + (size_t)b * TOT + keyoff;

    #pragma unroll
    for (int a = 0; a < 3; ++a) {
        const float s   = (float)(3 + a) * stride;
        const float hlf = 0.5f * s;
        const float ax1 = cxp - hlf, ay1 = cyp - hlf;
        const float ax2 = cxp + hlf, ay2 = cyp + hlf;
        const float areaA = s * s;

        // sequential argmax over surviving GTs (first-max tie-break preserved);
        // division-free: iou_j > iou_b  <=>  inter_j*S_b > inter_b*S_j
        float BI = 0.0f, BS = 1.0f; int BX = 0;
        for (int j = 0; j < cnt; ++j) {
            float4 g = s_cbox[j];
            float lx = fmaxf(ax1, g.x), ly = fmaxf(ay1, g.y);
            float rx = fminf(ax2, g.z), ry = fminf(ay2, g.w);
            float iw = fmaxf(rx - lx, 0.0f), ih = fmaxf(ry - ly, 0.0f);
            float inter = iw * ih;
            float S     = areaA + s_carea[j];
            if (inter * BS > BI * S) { BI = inter; BS = S; BX = j; }
        }

        const float denom    = (BS - BI) + 1e-9f;
        const float best_iou = BI / denom;
        const bool  pos = (best_iou >= 0.5f);
        const bool  neg = (best_iou <  0.4f);

        const size_t base = ((size_t)b * 24 + a * 8) * (size_t)HW + p;
        const float  xo   = pred[base + 4 * (size_t)HW];   // objectness logit
        const float  key  = neg ? xo : -1e30f;
        keyb[a * HW + p] = key;
        atomicAdd(&sh_hist[f2u(key) >> 20], 1u);

        if (pos) {
            cpos++;
            loss += fmaxf(xo, 0.0f) - xo + log1pf(expf(-fabsf(xo)));

            float4 g = s_cbox[BX];
            float gx = (g.x + g.z) * 0.5f;
            float gy = (g.y + g.w) * 0.5f;
            float gw = fmaxf(g.z - g.x, 1e-6f);
            float gh = fmaxf(g.w - g.y, 1e-6f);
            float aw = fmaxf(ax2 - ax1, 1e-6f);
            float ah = fmaxf(ay2 - ay1, 1e-6f);

            float ttx = (gx - cxp) / aw;
            float tty = (gy - cyp) / ah;
            float ttw = logf(gw / aw);
            float tth = logf(gh / ah);

            float p0 = pred[base];
            float p1 = pred[base + 1 * (size_t)HW];
            float p2 = pred[base + 2 * (size_t)HW];
            float p3 = pred[base + 3 * (size_t)HW];
            loss += sl1(p0 - ttx) + sl1(p1 - tty) + sl1(p2 - ttw) + sl1(p3 - tth);

            float c0 = pred[base + 5 * (size_t)HW];
            float c1 = pred[base + 6 * (size_t)HW];
            float c2 = pred[base + 7 * (size_t)HW];
            float m  = fmaxf(c0, fmaxf(c1, c2));
            float lse = m + logf(expf(c0 - m) + expf(c1 - m) + expf(c2 - m));
            int   t   = max(s_clbl[BX], 0);
            float pt  = (t == 0) ? c0 : ((t == 1) ? c1 : c2);
            loss += lse - pt;
        }
    }

    // block loss reduction
    #pragma unroll
    for (int o = 16; o; o >>= 1) {
        loss += __shfl_down_sync(0xFFFFFFFFu, loss, o);
        cpos += __shfl_down_sync(0xFFFFFFFFu, cpos, o);
    }
    const int wid = tid >> 5, lid = tid & 31;
    if (lid == 0) { rs[wid] = loss; rc[wid] = cpos; }
    __syncthreads();
    if (tid == 0) {
        float L = 0.0f; int C = 0;
        #pragma unroll
        for (int i = 0; i < 8; ++i) { L += rs[i]; C += rc[i]; }
        if (L != 0.0f) atomicAdd(&g_acc, (double)L);
        if (C)         atomicAdd(&g_numpos[b * 3 + scale], C);
    }

    // flush fused histogram (non-zero bins only)
    unsigned* gh = g_hist + (b * 3 + scale) * HB;
    for (int i = tid; i < HB; i += 256) {
        unsigned c = sh_hist[i];
        if (c) atomicAdd(&gh[i], c);
    }
}

// ---------------------------------------------------------------------------
// S2: per-task descending scan of the histogram -> 12-bit threshold bin + kk
// ---------------------------------------------------------------------------
__global__ __launch_bounds__(256) void k_plan() {
    const int task = blockIdx.x;
    const int s = task % 3;
    int N, off; task_dims(s, N, off);

    int k = 3 * max(1, g_numpos[task]);
    if (k > N) k = N;

    const unsigned* gh = g_hist + task * HB;
    int cnt[16], tot = 0;
    #pragma unroll
    for (int i = 0; i < 16; ++i) {
        int bin = HB - 1 - (threadIdx.x * 16 + i);
        cnt[i] = (int)gh[bin];
        tot += cnt[i];
    }
    int excl = scan256(tot);
    if (excl < k && excl + tot >= k) {
        int cum = excl;
        #pragma unroll
        for (int i = 0; i < 16; ++i) {
            if (cum + cnt[i] >= k) {
                g_planT[task]  = HB - 1 - (threadIdx.x * 16 + i);
                g_planKK[task] = k - cum;
                break;
            }
            cum += cnt[i];
        }
    }
}

// ---------------------------------------------------------------------------
// S3: parallel pass: sum softplus above threshold bin; compact bin members.
// grid=(12, NTASK)
// ---------------------------------------------------------------------------
__global__ __launch_bounds__(256) void k_sumgather() {
    __shared__ float rs[8];
    const int task = blockIdx.y;
    const int s = task % 3, b = task / 3;
    int N, off; task_dims(s, N, off);
    const int n4 = N >> 2;
    const int base4 = blockIdx.x * 1024;
    if (base4 >= n4) return;

    const unsigned T = (unsigned)g_planT[task];
    const uint4* keys4 = (const uint4*)(g_keys + (size_t)b * TOT + off);
    unsigned* buf = g_buf + (size_t)task * MAXN;

    float local = 0.0f;
    #pragma unroll
    for (int k = 0; k < 4; ++k) {
        int i4 = base4 + threadIdx.x + k * 256;
        if (i4 < n4) {
            uint4 v = keys4[i4];
            unsigned uu[4] = {f2u(__uint_as_float(v.x)), f2u(__uint_as_float(v.y)),
                              f2u(__uint_as_float(v.z)), f2u(__uint_as_float(v.w))};
            #pragma unroll
            for (int q = 0; q < 4; ++q) {
                unsigned bin = uu[q] >> 20;
                if (bin > T)       local += softplus0(key2f(uu[q]));
                else if (bin == T) buf[atomicAdd(&g_bufcnt[task], 1u)] = uu[q];
            }
        }
    }
    float tot = block_reduce(local, rs);
    if (threadIdx.x == 0 && tot != 0.0f) atomicAdd(&g_acc, (double)tot);
}

// ---------------------------------------------------------------------------
// S4: per-task exact refinement over compacted bin members (12 + 8 low bits)
// ---------------------------------------------------------------------------
__global__ __launch_bounds__(256) void k_refine() {
    __shared__ unsigned h2[HB];
    __shared__ unsigned h3[256];
    __shared__ float    rs[8];
    __shared__ int      sT2, sKK2, sT3, sKK3;

    const int task = blockIdx.x;
    const int m  = (int)g_bufcnt[task];
    const int kk = g_planKK[task];
    const unsigned top12 = (unsigned)g_planT[task];
    const unsigned* buf = g_buf + (size_t)task * MAXN;

    for (int i = threadIdx.x; i < HB; i += 256) h2[i] = 0;
    h3[threadIdx.x] = 0;
    __syncthreads();

    for (int i = threadIdx.x; i < m; i += 256)
        atomicAdd(&h2[(buf[i] >> 8) & 0xFFFu], 1u);
    __syncthreads();

    {
        int cnt[16], tot = 0;
        #pragma unroll
        for (int i = 0; i < 16; ++i) {
            int bin = HB - 1 - (threadIdx.x * 16 + i);
            cnt[i] = (int)h2[bin];
            tot += cnt[i];
        }
        int excl = scan256(tot);
        if (excl < kk && excl + tot >= kk) {
            int cum = excl;
            #pragma unroll
            for (int i = 0; i < 16; ++i) {
                if (cum + cnt[i] >= kk) { sT2 = HB - 1 - (threadIdx.x * 16 + i); sKK2 = kk - cum; break; }
                cum += cnt[i];
            }
        }
    }
    __syncthreads();
    const unsigned T2 = (unsigned)sT2;
    const int kk2 = sKK2;

    float local = 0.0f;
    for (int i = threadIdx.x; i < m; i += 256) {
        unsigned u = buf[i];
        unsigned mid = (u >> 8) & 0xFFFu;
        if (mid > T2)       local += softplus0(key2f(u));
        else if (mid == T2) atomicAdd(&h3[u & 0xFFu], 1u);
    }
    __syncthreads();

    {
        int bin = 255 - threadIdx.x;
        int c = (int)h3[bin];
        int excl = scan256(c);
        if (excl < kk2 && excl + c >= kk2) { sT3 = bin; sKK3 = kk2 - excl; }
    }
    __syncthreads();
    const unsigned T3 = (unsigned)sT3;
    const int kk3 = sKK3;
    const unsigned ustar = (top12 << 20) | (T2 << 8) | T3;

    for (int i = threadIdx.x; i < m; i += 256) {
        unsigned u = buf[i];
        if (((u >> 8) & 0xFFFu) == T2 && (u & 0xFFu) > T3)
            local += softplus0(key2f(u));
    }
    __syncthreads();
    float tot = block_reduce(local, rs);
    if (threadIdx.x == 0) {
        tot += (float)kk3 * softplus0(key2f(ustar));
        atomicAdd(&g_acc, (double)tot);
    }
}

__global__ void k_fin(float* out) {
    out[0] = (float)(g_acc * (1.0 / 64.0));
}

extern "C" void kernel_launch(void* const* d_in, const int* in_sizes, int n_in,
                              void* d_out, int out_size)
{
    const float* pred0 = (const float*)d_in[0];
    const float* pred1 = (const float*)d_in[2];
    const float* pred2 = (const float*)d_in[4];
    const float* gtb   = (const float*)d_in[6];
    const int*   gtl   = (const int*)d_in[7];

    k_init<<<1536, 512>>>();

    dim3 ga(84, NB);
    k_assign<<<ga, 256>>>(pred0, pred1, pred2, gtb, gtl);

    k_plan<<<NTASK, 256>>>();
    dim3 gh(12, NTASK);
    k_sumgather<<<gh, 256>>>();
    k_refine<<<NTASK, 256>>>();
    k_fin<<<1, 1>>>((float*)d_out);
}